// round 5
// baseline (speedup 1.0000x reference)
#include <cuda_runtime.h>
#include <cuda_bf16.h>
#include <cstdint>

#define NN 8192
#define FD 256
#define HD 64
#define HE 80      // padded h_ext columns (64 h + 1 ones + 15 zero)
#define NTC 72     // C columns (64 h-cols + deg at 64 + pad)
#define BM 64
#define BK 64
#define NIT (NN / BK)          // 128 k-tiles
#define STAGES 4
#define SB_STR 88              // bf16 per sB row (conflict-free ldmatrix)
#define SB_TILE (BK * SB_STR)  // 5632 bf16 = 11264 B

// device scratch (static allocation only — no cudaMalloc allowed)
__device__ __align__(16) __nv_bfloat16 g_hext[NN * HE];
__device__ __align__(16) float g_C[NN * NTC];

typedef unsigned int uint;

__device__ __forceinline__ void cpa16(void* dst, const void* src) {
    uint32_t d = (uint32_t)__cvta_generic_to_shared(dst);
    asm volatile("cp.async.cg.shared.global [%0], [%1], 16;\n" :: "r"(d), "l"(src));
}

// ---------------------------------------------------------------------------
// K_h: h = x @ Wt^T + bt  ->  g_hext (bf16, 80 cols; col 64 = 1.0, rest 0)
// 512 thr: c = tid&63, fc = tid>>6 (8 f-chunks of 32) -> only 32 w-regs/thread.
// ---------------------------------------------------------------------------
__global__ void __launch_bounds__(512) k_h(const float* __restrict__ x,
                                           const float* __restrict__ Wt,
                                           const float* __restrict__ bt) {
    __shared__ __align__(16) float xs[16][FD];      // 16 KB
    __shared__ float part[8][16][64];               // 32 KB
    const int tid = threadIdx.x;
    const int c = tid & 63;        // output column
    const int fc = tid >> 6;       // f-chunk 0..7

    float w[32];
    {
        const float4* wr = (const float4*)(Wt + (size_t)c * FD + fc * 32);
#pragma unroll
        for (int j = 0; j < 8; j++) {
            float4 v = wr[j];
            w[4 * j] = v.x; w[4 * j + 1] = v.y; w[4 * j + 2] = v.z; w[4 * j + 3] = v.w;
        }
    }

    const int r0 = blockIdx.x * 16;   // grid 512 covers 8192
#pragma unroll
    for (int j = 0; j < 8; j++) {
        int i = tid + j * 512;
        int r = i >> 8, f = i & 255;
        xs[r][f] = x[(size_t)(r0 + r) * FD + f];
    }
    __syncthreads();

#pragma unroll
    for (int r = 0; r < 16; r++) {
        const float4* xv = (const float4*)(&xs[r][fc * 32]);
        float p = 0.f;
#pragma unroll
        for (int j = 0; j < 8; j++) {
            float4 v = xv[j];
            p += v.x * w[4 * j] + v.y * w[4 * j + 1] + v.z * w[4 * j + 2] + v.w * w[4 * j + 3];
        }
        part[fc][r][c] = p;
    }
    __syncthreads();

#pragma unroll
    for (int j = 0; j < 2; j++) {
        int i = tid + j * 512;
        int r = i >> 6, cc = i & 63;
        float hv = bt[cc];
#pragma unroll
        for (int f = 0; f < 8; f++) hv += part[f][r][cc];
        g_hext[(size_t)(r0 + r) * HE + cc] = __float2bfloat16(hv);
    }
    if (tid < 256) {   // pad cols 64..79 (col 64 = ones for deg)
        int r = tid >> 4, cc = 64 + (tid & 15);
        g_hext[(size_t)(r0 + r) * HE + cc] = __float2bfloat16(cc == HD ? 1.f : 0.f);
    }
}

// ---------------------------------------------------------------------------
// K_mm: C[8192, 72] = adj(0/1 -> bf16) @ h_ext   via mma.sync m16n8k16
//  - A fragments loaded DIRECTLY from gmem (LDG.64 int2 per frag pair),
//    packed to bf16 in registers; 2-deep register prefetch. Zero A smem.
//  - B (h_ext) via 4-stage cp.async pipeline + ldmatrix (45 KB static smem)
//  - col 64 of h_ext = 1.0 -> C[:,64] = deg (exact fp32 accum)
// ---------------------------------------------------------------------------
__device__ __forceinline__ void loadB(__nv_bfloat16* sB, int kt, int tid) {
#pragma unroll
    for (int j = 0; j < 3; j++) {
        int i = tid + j * 256;          // 640 chunks of 16B (h_ext 64x80 bf16)
        if (i < 640) {
            int r = i / 10, cc = i % 10;
            cpa16(sB + r * SB_STR + cc * 8, g_hext + (size_t)(kt * BK + r) * HE + cc * 8);
        }
    }
    asm volatile("cp.async.commit_group;\n");
}

__device__ __forceinline__ void loadA(int2* dst, const int* __restrict__ bp, int kt) {
    const int* p = bp + (size_t)kt * BK;
#pragma unroll
    for (int ks = 0; ks < 4; ks++) {
        dst[4 * ks + 0] = *(const int2*)(p + ks * 16);
        dst[4 * ks + 1] = *(const int2*)(p + ks * 16 + 8 * NN);
        dst[4 * ks + 2] = *(const int2*)(p + ks * 16 + 8);
        dst[4 * ks + 3] = *(const int2*)(p + ks * 16 + 8 * NN + 8);
    }
}

__global__ void __launch_bounds__(256) k_adj_mm(const int* __restrict__ adj) {
    __shared__ __align__(16) __nv_bfloat16 sB0[STAGES * SB_TILE];  // 45 KB

    const int tid = threadIdx.x;
    const int warp = tid >> 5, lane = tid & 31;
    const int rowBase = blockIdx.x * BM;
    const int mrow = (warp & 3) * 16;     // 4 row-groups of 16
    const int nset = warp >> 2;           // 0: cols 0-39 (tiles 0-4), 1: cols 40-71
    const int fr = lane >> 2;             // fragment row within 8
    const int fcol = (lane & 3) * 2;      // fragment col pair base

    const int* bp = adj + (size_t)(rowBase + mrow + fr) * NN + fcol;

    float acc[5][4];
#pragma unroll
    for (int i = 0; i < 5; i++) { acc[i][0] = acc[i][1] = acc[i][2] = acc[i][3] = 0.f; }

    int2 pA0[16], pA1[16];
    loadA(pA0, bp, 0);
    loadA(pA1, bp, 1);
    loadB(sB0 + 0 * SB_TILE, 0, tid);
    loadB(sB0 + 1 * SB_TILE, 1, tid);
    loadB(sB0 + 2 * SB_TILE, 2, tid);

    for (int kt = 0; kt < NIT; ++kt) {
        // pack current A prefetch regs -> bf16 fragments
        uint a[4][4];
        {
            const int2* pc = (kt & 1) ? pA1 : pA0;
#pragma unroll
            for (int ks = 0; ks < 4; ks++) {
#pragma unroll
                for (int j = 0; j < 4; j++) {
                    int2 p = pc[4 * ks + j];
                    a[ks][j] = (uint)p.x * 0x3F80u + (uint)p.y * 0x3F800000u;
                }
            }
        }
        // prefetch A for kt+2 into the buffer just consumed
        if (kt + 2 < NIT) loadA((kt & 1) ? pA1 : pA0, bp, kt + 2);

        asm volatile("cp.async.wait_group %0;\n" :: "n"(STAGES - 2));
        __syncthreads();
        if (kt + STAGES - 1 < NIT)
            loadB(sB0 + ((kt + STAGES - 1) & (STAGES - 1)) * SB_TILE, kt + STAGES - 1, tid);

        const __nv_bfloat16* sB = sB0 + (kt & (STAGES - 1)) * SB_TILE;

#pragma unroll
        for (int ks = 0; ks < 4; ++ks) {
            const int kk = ks * 16 + (lane & 15);
#pragma unroll
            for (int pl = 0; pl < 2; ++pl) {          // two x4 ldmatrix per nset
                const int colb = nset * 40 + pl * 16; // nset0: 0,16  nset1: 40,56
                uint b0, b1, b2, b3;
                uint32_t addr = (uint32_t)__cvta_generic_to_shared(
                    &sB[kk * SB_STR + colb + ((lane >> 4) << 3)]);
                asm volatile("ldmatrix.sync.aligned.m8n8.x4.trans.shared.b16 {%0,%1,%2,%3},[%4];\n"
                             : "=r"(b0), "=r"(b1), "=r"(b2), "=r"(b3) : "r"(addr));
                asm volatile("mma.sync.aligned.m16n8k16.row.col.f32.bf16.bf16.f32 "
                             "{%0,%1,%2,%3},{%4,%5,%6,%7},{%8,%9},{%0,%1,%2,%3};\n"
                             : "+f"(acc[pl * 2][0]), "+f"(acc[pl * 2][1]),
                               "+f"(acc[pl * 2][2]), "+f"(acc[pl * 2][3])
                             : "r"(a[ks][0]), "r"(a[ks][1]), "r"(a[ks][2]), "r"(a[ks][3]),
                               "r"(b0), "r"(b1));
                asm volatile("mma.sync.aligned.m16n8k16.row.col.f32.bf16.bf16.f32 "
                             "{%0,%1,%2,%3},{%4,%5,%6,%7},{%8,%9},{%0,%1,%2,%3};\n"
                             : "+f"(acc[pl * 2 + 1][0]), "+f"(acc[pl * 2 + 1][1]),
                               "+f"(acc[pl * 2 + 1][2]), "+f"(acc[pl * 2 + 1][3])
                             : "r"(a[ks][0]), "r"(a[ks][1]), "r"(a[ks][2]), "r"(a[ks][3]),
                               "r"(b2), "r"(b3));
            }
            if (nset == 0) {   // tile 4: cols 32-39
                uint b0, b1;
                uint32_t addr = (uint32_t)__cvta_generic_to_shared(&sB[kk * SB_STR + 32]);
                asm volatile("ldmatrix.sync.aligned.m8n8.x2.trans.shared.b16 {%0,%1},[%2];\n"
                             : "=r"(b0), "=r"(b1) : "r"(addr));
                asm volatile("mma.sync.aligned.m16n8k16.row.col.f32.bf16.bf16.f32 "
                             "{%0,%1,%2,%3},{%4,%5,%6,%7},{%8,%9},{%0,%1,%2,%3};\n"
                             : "+f"(acc[4][0]), "+f"(acc[4][1]), "+f"(acc[4][2]), "+f"(acc[4][3])
                             : "r"(a[ks][0]), "r"(a[ks][1]), "r"(a[ks][2]), "r"(a[ks][3]),
                               "r"(b0), "r"(b1));
            }
        }
        __syncthreads();
    }

    // store C tile
    const int gr = lane >> 2, gc = (lane & 3) * 2;
    const int ntiles = (nset == 0) ? 5 : 4;
#pragma unroll
    for (int lt = 0; lt < 5; ++lt) {
        if (lt >= ntiles) break;
        const int gt = (nset == 0) ? lt : (5 + lt);
        size_t base = (size_t)(rowBase + mrow + gr) * NTC + gt * 8 + gc;
        g_C[base] = acc[lt][0];
        g_C[base + 1] = acc[lt][1];
        g_C[base + (size_t)8 * NTC] = acc[lt][2];
        g_C[base + (size_t)8 * NTC + 1] = acc[lt][3];
    }
}

// ---------------------------------------------------------------------------
// K_epi: 16 rows per CTA.  neighbor = C[:, :64]/deg; tf = neighbor @ Wp^T + bp;
//        y = x + tf; LayerNorm(y) -> out.
// ---------------------------------------------------------------------------
__global__ void __launch_bounds__(256) k_epi(const float* __restrict__ x,
                                             const float* __restrict__ Wp,
                                             const float* __restrict__ bp,
                                             const float* __restrict__ gamma,
                                             const float* __restrict__ beta,
                                             float* __restrict__ out) {
    __shared__ __align__(16) float nb[16][HD];   // 4 KB
    __shared__ float pwS[8][16], pwQ[8][16];
    __shared__ float muS[16], rsS[16];
    const int row0 = blockIdx.x * 16;
    const int t = threadIdx.x;
    const int warp = t >> 5, lane = t & 31;

#pragma unroll
    for (int j = 0; j < 4; j++) {
        int i = t + j * 256;
        int r = i >> 6, cc = i & 63;
        float deg = g_C[(size_t)(row0 + r) * NTC + HD];
        float v = g_C[(size_t)(row0 + r) * NTC + cc];
        nb[r][cc] = (deg > 0.5f) ? v / deg : 0.f;
    }
    __syncthreads();

    float tf[16];
    {
        float b = bp[t];
#pragma unroll
        for (int r = 0; r < 16; r++) tf[r] = b;
    }
    const float4* wp4 = (const float4*)(Wp + (size_t)t * HD);
#pragma unroll
    for (int q = 0; q < 16; q++) {
        float4 w = wp4[q];
#pragma unroll
        for (int r = 0; r < 16; r++) {
            float4 nv = *(const float4*)(&nb[r][q * 4]);
            tf[r] += nv.x * w.x + nv.y * w.y + nv.z * w.z + nv.w * w.w;
        }
    }

    float y[16];
#pragma unroll
    for (int r = 0; r < 16; r++) y[r] = x[(size_t)(row0 + r) * FD + t] + tf[r];

#pragma unroll
    for (int r = 0; r < 16; r++) {
        float s = y[r], q = y[r] * y[r];
#pragma unroll
        for (int o = 16; o > 0; o >>= 1) {
            s += __shfl_xor_sync(0xffffffffu, s, o);
            q += __shfl_xor_sync(0xffffffffu, q, o);
        }
        if (lane == 0) { pwS[warp][r] = s; pwQ[warp][r] = q; }
    }
    __syncthreads();
    if (t < 16) {
        float s = 0.f, q = 0.f;
#pragma unroll
        for (int w = 0; w < 8; w++) { s += pwS[w][t]; q += pwQ[w][t]; }
        float mu = s * (1.f / FD);
        float var = q * (1.f / FD) - mu * mu;
        muS[t] = mu;
        rsS[t] = rsqrtf(var + 1e-5f);
    }
    __syncthreads();

    const float g = gamma[t], b = beta[t];
#pragma unroll
    for (int r = 0; r < 16; r++)
        out[(size_t)(row0 + r) * FD + t] = g * (y[r] - muS[r]) * rsS[r] + b;
}

// ---------------------------------------------------------------------------
extern "C" void kernel_launch(void* const* d_in, const int* in_sizes, int n_in,
                              void* d_out, int out_size) {
    const float* x     = (const float*)d_in[0];
    const int*   adj   = (const int*)d_in[1];
    const float* Wt    = (const float*)d_in[2];
    const float* bt    = (const float*)d_in[3];
    // d_in[4] (Wa), d_in[5] (ba): mathematically irrelevant — softmax over
    // row-constant scores collapses to 1/deg regardless of s.
    const float* Wp    = (const float*)d_in[6];
    const float* bp    = (const float*)d_in[7];
    const float* gamma = (const float*)d_in[8];
    const float* beta  = (const float*)d_in[9];
    float* out = (float*)d_out;

    k_h<<<NN / 16, 512>>>(x, Wt, bt);
    k_adj_mm<<<NN / BM, 256>>>(adj);
    k_epi<<<NN / 16, 256>>>(x, Wp, bp, gamma, beta, out);
}

// round 8
// speedup vs baseline: 1.9210x; 1.9210x over previous
#include <cuda_runtime.h>
#include <cuda_bf16.h>
#include <cstdint>

#define NN 8192
#define FD 256
#define HD 64
#define HE 80      // h_ext columns (64 h + ones col 64 + 15 zero)
#define NTC 72     // C columns (deg at col 64)
#define BM 128
#define BK 64
#define KSPLIT 2
#define NITL (NN / BK / KSPLIT)   // 64 k-tiles per CTA
#define SB_STR 88                 // bf16 per sB row (conflict-free ldmatrix)
#define SB_TILE (BK * SB_STR)     // 5632 bf16 = 11264 B
#define SA_BYTES (BM * 128)       // 16384 B per A buffer (swizzled, 128B rows)
#define SMEM_MM (2 * SA_BYTES + 3 * SB_TILE * 2)  // 32768 + 33792 = 66560

// device scratch (static allocation only — no cudaMalloc allowed)
__device__ __align__(16) __nv_bfloat16 g_hext[NN * HE];
__device__ __align__(16) float g_Cp[KSPLIT * NN * NTC];

typedef unsigned int uint;

__device__ __forceinline__ void cpa16(void* dst, const void* src) {
    uint32_t d = (uint32_t)__cvta_generic_to_shared(dst);
    asm volatile("cp.async.cg.shared.global [%0], [%1], 16;\n" :: "r"(d), "l"(src));
}

// ---------------------------------------------------------------------------
// K_h: h = x @ Wt^T + bt  ->  g_hext (bf16, 80 cols; col 64 = 1.0, rest 0)
// 512 thr; 4 accumulators break the FFMA dependency chain.
// ---------------------------------------------------------------------------
__global__ void __launch_bounds__(512) k_h(const float* __restrict__ x,
                                           const float* __restrict__ Wt,
                                           const float* __restrict__ bt) {
    __shared__ __align__(16) float xs[16][FD];      // 16 KB
    __shared__ float part[8][16][64];               // 32 KB
    const int tid = threadIdx.x;
    const int c = tid & 63;        // output column
    const int fc = tid >> 6;       // f-chunk 0..7

    float w[32];
    {
        const float4* wr = (const float4*)(Wt + (size_t)c * FD + fc * 32);
#pragma unroll
        for (int j = 0; j < 8; j++) {
            float4 v = wr[j];
            w[4 * j] = v.x; w[4 * j + 1] = v.y; w[4 * j + 2] = v.z; w[4 * j + 3] = v.w;
        }
    }

    const int r0 = blockIdx.x * 16;   // grid 512 covers 8192
#pragma unroll
    for (int j = 0; j < 8; j++) {
        int i = tid + j * 512;
        int r = i >> 8, f = i & 255;
        xs[r][f] = x[(size_t)(r0 + r) * FD + f];
    }
    __syncthreads();

#pragma unroll
    for (int r = 0; r < 16; r++) {
        const float4* xv = (const float4*)(&xs[r][fc * 32]);
        float p0 = 0.f, p1 = 0.f, p2 = 0.f, p3 = 0.f;
#pragma unroll
        for (int j = 0; j < 8; j += 4) {
            float4 v0 = xv[j], v1 = xv[j + 1], v2 = xv[j + 2], v3 = xv[j + 3];
            p0 += v0.x * w[4 * j + 0] + v0.y * w[4 * j + 1] + v0.z * w[4 * j + 2] + v0.w * w[4 * j + 3];
            p1 += v1.x * w[4 * j + 4] + v1.y * w[4 * j + 5] + v1.z * w[4 * j + 6] + v1.w * w[4 * j + 7];
            p2 += v2.x * w[4 * j + 8] + v2.y * w[4 * j + 9] + v2.z * w[4 * j + 10] + v2.w * w[4 * j + 11];
            p3 += v3.x * w[4 * j + 12] + v3.y * w[4 * j + 13] + v3.z * w[4 * j + 14] + v3.w * w[4 * j + 15];
        }
        part[fc][r][c] = (p0 + p1) + (p2 + p3);
    }
    __syncthreads();

#pragma unroll
    for (int j = 0; j < 2; j++) {
        int i = tid + j * 512;
        int r = i >> 6, cc = i & 63;
        float hv = bt[cc];
#pragma unroll
        for (int f = 0; f < 8; f++) hv += part[f][r][cc];
        g_hext[(size_t)(r0 + r) * HE + cc] = __float2bfloat16(hv);
    }
    if (tid < 256) {   // pad cols 64..79 (col 64 = ones for deg)
        int r = tid >> 4, cc = 64 + (tid & 15);
        g_hext[(size_t)(r0 + r) * HE + cc] = __float2bfloat16(cc == HD ? 1.f : 0.f);
    }
}

// ---------------------------------------------------------------------------
// K_mm: Cp[khalf] = adj(0/1 -> bf16) @ h_ext over k-half   (mma.sync m16n8k16)
//  - BM=128, split-K=2 -> grid 128 (1 CTA/SM), 256 thr
//  - warps: mgroup=warp&3 (32 rows = 2 m-frags), nset=warp>>2 (cols 0-39 / 40-71)
//  - A: LDG int4 -> reg bf16 pack -> XOR-swizzled STS.128 (conflict-free),
//    double-buffered; A-ldmatrix uses same swizzle
//  - B: 3-stage cp.async ring (R3-validated layout)
// ---------------------------------------------------------------------------
__device__ __forceinline__ void loadB(__nv_bfloat16* sB, int ktg, int tid) {
#pragma unroll
    for (int j = 0; j < 3; j++) {
        int i = tid + j * 256;          // 640 chunks of 16B (h_ext 64x80 bf16)
        if (i < 640) {
            int r = i / 10, cc = i % 10;
            cpa16(sB + r * SB_STR + cc * 8, g_hext + (size_t)(ktg * BK + r) * HE + cc * 8);
        }
    }
    asm volatile("cp.async.commit_group;\n");
}

__global__ void __launch_bounds__(256) k_adj_mm(const int* __restrict__ adj) {
    extern __shared__ __align__(16) char dyn[];
    char* sA = dyn;                                          // 2 x 16384 B
    __nv_bfloat16* sB0 = (__nv_bfloat16*)(dyn + 2 * SA_BYTES);

    const int tid = threadIdx.x;
    const int warp = tid >> 5, lane = tid & 31;
    const int mtile = blockIdx.x >> 1, khalf = blockIdx.x & 1;
    const int rowBase = mtile * BM;
    const int kbase = khalf * (NN / 2);
    const int mgroup = warp & 3;          // 32-row group
    const int nset = warp >> 2;           // 0: tiles 0-4 (cols 0-39), 1: tiles 5-8

    // A producer mapping: 2 threads per row
    const int m = tid >> 1;               // 0..127
    const int kh = tid & 1;               // 32-int half
    const int* ap = adj + (size_t)(rowBase + m) * NN + kbase + kh * 32;

    float acc[2][5][4];
#pragma unroll
    for (int a = 0; a < 2; a++)
#pragma unroll
        for (int i = 0; i < 5; i++)
            acc[a][i][0] = acc[a][i][1] = acc[a][i][2] = acc[a][i][3] = 0.f;

    int4 rA[8];
#pragma unroll
    for (int q = 0; q < 8; q++) rA[q] = ((const int4*)ap)[q];

    loadB(sB0 + 0 * SB_TILE, khalf * NITL + 0, tid);
    loadB(sB0 + 1 * SB_TILE, khalf * NITL + 1, tid);

    const uint32_t sAu = (uint32_t)__cvta_generic_to_shared(sA);

    for (int kt = 0; kt < NITL; ++kt) {
        // pack A regs -> bf16, swizzled STS.128 (4 per thread)
        {
            const uint32_t abase = sAu + (kt & 1) * SA_BYTES + m * 128;
#pragma unroll
            for (int j = 0; j < 4; j++) {
                int4 v0 = rA[2 * j], v1 = rA[2 * j + 1];
                uint w0 = (uint)v0.x * 0x3F80u + (uint)v0.y * 0x3F800000u;
                uint w1 = (uint)v0.z * 0x3F80u + (uint)v0.w * 0x3F800000u;
                uint w2 = (uint)v1.x * 0x3F80u + (uint)v1.y * 0x3F800000u;
                uint w3 = (uint)v1.z * 0x3F80u + (uint)v1.w * 0x3F800000u;
                int cs = (kh * 4 + j) ^ (m & 7);
                asm volatile("st.shared.v4.b32 [%0], {%1, %2, %3, %4};"
                             :: "r"(abase + cs * 16), "r"(w0), "r"(w1), "r"(w2), "r"(w3)
                             : "memory");
            }
        }
        // prefetch A for kt+1
        if (kt + 1 < NITL) {
            const int4* nsrc = (const int4*)(ap + (size_t)(kt + 1) * BK);
#pragma unroll
            for (int q = 0; q < 8; q++) rA[q] = nsrc[q];
        }

        asm volatile("cp.async.wait_group 1;\n");
        __syncthreads();
        if (kt + 2 < NITL)
            loadB(sB0 + ((kt + 2) % 3) * SB_TILE, khalf * NITL + kt + 2, tid);

        const __nv_bfloat16* sB = sB0 + (kt % 3) * SB_TILE;
        const uint32_t sAb = sAu + (kt & 1) * SA_BYTES;

#pragma unroll
        for (int ks = 0; ks < 4; ++ks) {
            // A fragments for both m-frags (swizzled ldmatrix)
            uint a[2][4];
#pragma unroll
            for (int mf = 0; mf < 2; mf++) {
                int row = mgroup * 32 + mf * 16 + (lane & 15);
                int chunk = 2 * ks + (lane >> 4);
                uint32_t addr = sAb + row * 128 + ((chunk ^ (lane & 7)) * 16);
                asm volatile("ldmatrix.sync.aligned.m8n8.x4.shared.b16 {%0,%1,%2,%3},[%4];\n"
                             : "=r"(a[mf][0]), "=r"(a[mf][1]), "=r"(a[mf][2]), "=r"(a[mf][3])
                             : "r"(addr));
            }
            const int kk = ks * 16 + (lane & 15);
            if (nset == 0) {
                uint b[10];
#pragma unroll
                for (int pl = 0; pl < 2; pl++) {
                    uint32_t addr = (uint32_t)__cvta_generic_to_shared(
                        &sB[kk * SB_STR + pl * 16 + ((lane >> 4) << 3)]);
                    asm volatile("ldmatrix.sync.aligned.m8n8.x4.trans.shared.b16 {%0,%1,%2,%3},[%4];\n"
                                 : "=r"(b[4 * pl]), "=r"(b[4 * pl + 1]),
                                   "=r"(b[4 * pl + 2]), "=r"(b[4 * pl + 3])
                                 : "r"(addr));
                }
                {
                    uint32_t addr = (uint32_t)__cvta_generic_to_shared(&sB[kk * SB_STR + 32]);
                    asm volatile("ldmatrix.sync.aligned.m8n8.x2.trans.shared.b16 {%0,%1},[%2];\n"
                                 : "=r"(b[8]), "=r"(b[9]) : "r"(addr));
                }
#pragma unroll
                for (int mf = 0; mf < 2; mf++) {
#pragma unroll
                    for (int t = 0; t < 5; t++) {
                        asm volatile("mma.sync.aligned.m16n8k16.row.col.f32.bf16.bf16.f32 "
                                     "{%0,%1,%2,%3},{%4,%5,%6,%7},{%8,%9},{%0,%1,%2,%3};\n"
                                     : "+f"(acc[mf][t][0]), "+f"(acc[mf][t][1]),
                                       "+f"(acc[mf][t][2]), "+f"(acc[mf][t][3])
                                     : "r"(a[mf][0]), "r"(a[mf][1]), "r"(a[mf][2]), "r"(a[mf][3]),
                                       "r"(b[2 * t]), "r"(b[2 * t + 1]));
                    }
                }
            } else {
                uint b[8];
#pragma unroll
                for (int pl = 0; pl < 2; pl++) {
                    uint32_t addr = (uint32_t)__cvta_generic_to_shared(
                        &sB[kk * SB_STR + 40 + pl * 16 + ((lane >> 4) << 3)]);
                    asm volatile("ldmatrix.sync.aligned.m8n8.x4.trans.shared.b16 {%0,%1,%2,%3},[%4];\n"
                                 : "=r"(b[4 * pl]), "=r"(b[4 * pl + 1]),
                                   "=r"(b[4 * pl + 2]), "=r"(b[4 * pl + 3])
                                 : "r"(addr));
                }
#pragma unroll
                for (int mf = 0; mf < 2; mf++) {
#pragma unroll
                    for (int t = 0; t < 4; t++) {
                        asm volatile("mma.sync.aligned.m16n8k16.row.col.f32.bf16.bf16.f32 "
                                     "{%0,%1,%2,%3},{%4,%5,%6,%7},{%8,%9},{%0,%1,%2,%3};\n"
                                     : "+f"(acc[mf][t][0]), "+f"(acc[mf][t][1]),
                                       "+f"(acc[mf][t][2]), "+f"(acc[mf][t][3])
                                     : "r"(a[mf][0]), "r"(a[mf][1]), "r"(a[mf][2]), "r"(a[mf][3]),
                                       "r"(b[2 * t]), "r"(b[2 * t + 1]));
                    }
                }
            }
        }
        // no trailing sync needed: next iter writes the other sA buffer, and
        // its pre-mma sync orders everything else.
    }

    // store C tile for this k-half
    float* Cout = g_Cp + (size_t)khalf * NN * NTC;
    const int gr = lane >> 2, gc = (lane & 3) * 2;
    const int ntiles = (nset == 0) ? 5 : 4;
#pragma unroll
    for (int mf = 0; mf < 2; mf++) {
#pragma unroll
        for (int lt = 0; lt < 5; ++lt) {
            if (lt >= ntiles) break;
            const int gt = (nset == 0) ? lt : (5 + lt);
            size_t base = (size_t)(rowBase + mgroup * 32 + mf * 16 + gr) * NTC + gt * 8 + gc;
            Cout[base] = acc[mf][lt][0];
            Cout[base + 1] = acc[mf][lt][1];
            Cout[base + (size_t)8 * NTC] = acc[mf][lt][2];
            Cout[base + (size_t)8 * NTC + 1] = acc[mf][lt][3];
        }
    }
}

// ---------------------------------------------------------------------------
// K_epi: 16 rows per CTA. C = Cp0 + Cp1; neighbor = C[:, :64]/deg;
//        tf = neighbor @ Wp^T + bp; y = x + tf; LayerNorm(y) -> out.
// ---------------------------------------------------------------------------
__global__ void __launch_bounds__(256) k_epi(const float* __restrict__ x,
                                             const float* __restrict__ Wp,
                                             const float* __restrict__ bp,
                                             const float* __restrict__ gamma,
                                             const float* __restrict__ beta,
                                             float* __restrict__ out) {
    __shared__ __align__(16) float nb[16][HD];
    __shared__ float pwS[8][16], pwQ[8][16];
    __shared__ float muS[16], rsS[16];
    const int row0 = blockIdx.x * 16;
    const int t = threadIdx.x;
    const int warp = t >> 5, lane = t & 31;
    const float* C0 = g_Cp;
    const float* C1 = g_Cp + (size_t)NN * NTC;

#pragma unroll
    for (int j = 0; j < 4; j++) {
        int i = t + j * 256;
        int r = i >> 6, cc = i & 63;
        size_t rb = (size_t)(row0 + r) * NTC;
        float deg = C0[rb + HD] + C1[rb + HD];
        float v = C0[rb + cc] + C1[rb + cc];
        nb[r][cc] = (deg > 0.5f) ? v / deg : 0.f;
    }
    __syncthreads();

    float tf[16];
    {
        float b = bp[t];
#pragma unroll
        for (int r = 0; r < 16; r++) tf[r] = b;
    }
    const float4* wp4 = (const float4*)(Wp + (size_t)t * HD);
#pragma unroll
    for (int q = 0; q < 16; q++) {
        float4 w = wp4[q];
#pragma unroll
        for (int r = 0; r < 16; r++) {
            float4 nv = *(const float4*)(&nb[r][q * 4]);
            tf[r] += nv.x * w.x + nv.y * w.y + nv.z * w.z + nv.w * w.w;
        }
    }

    float y[16];
#pragma unroll
    for (int r = 0; r < 16; r++) y[r] = x[(size_t)(row0 + r) * FD + t] + tf[r];

#pragma unroll
    for (int r = 0; r < 16; r++) {
        float s = y[r], q = y[r] * y[r];
#pragma unroll
        for (int o = 16; o > 0; o >>= 1) {
            s += __shfl_xor_sync(0xffffffffu, s, o);
            q += __shfl_xor_sync(0xffffffffu, q, o);
        }
        if (lane == 0) { pwS[warp][r] = s; pwQ[warp][r] = q; }
    }
    __syncthreads();
    if (t < 16) {
        float s = 0.f, q = 0.f;
#pragma unroll
        for (int w = 0; w < 8; w++) { s += pwS[w][t]; q += pwQ[w][t]; }
        float mu = s * (1.f / FD);
        float var = q * (1.f / FD) - mu * mu;
        muS[t] = mu;
        rsS[t] = rsqrtf(var + 1e-5f);
    }
    __syncthreads();

    const float g = gamma[t], b = beta[t];
#pragma unroll
    for (int r = 0; r < 16; r++)
        out[(size_t)(row0 + r) * FD + t] = g * (y[r] - muS[r]) * rsS[r] + b;
}

// ---------------------------------------------------------------------------
extern "C" void kernel_launch(void* const* d_in, const int* in_sizes, int n_in,
                              void* d_out, int out_size) {
    const float* x     = (const float*)d_in[0];
    const int*   adj   = (const int*)d_in[1];
    const float* Wt    = (const float*)d_in[2];
    const float* bt    = (const float*)d_in[3];
    // d_in[4] (Wa), d_in[5] (ba): mathematically irrelevant — softmax over
    // row-constant scores collapses to 1/deg regardless of s.
    const float* Wp    = (const float*)d_in[6];
    const float* bp    = (const float*)d_in[7];
    const float* gamma = (const float*)d_in[8];
    const float* beta  = (const float*)d_in[9];
    float* out = (float*)d_out;

    cudaFuncSetAttribute(k_adj_mm, cudaFuncAttributeMaxDynamicSharedMemorySize, SMEM_MM);
    k_h<<<NN / 16, 512>>>(x, Wt, bt);
    k_adj_mm<<<(NN / BM) * KSPLIT, 256, SMEM_MM>>>(adj);
    k_epi<<<NN / 16, 256>>>(x, Wp, bp, gamma, beta, out);
}

// round 9
// speedup vs baseline: 2.3817x; 1.2398x over previous
#include <cuda_runtime.h>
#include <cuda_bf16.h>
#include <cstdint>

#define NN 8192
#define FD 256
#define HD 64
#define HE 80      // h_ext columns (64 h + ones col 64 + 15 zero)
#define NTC 72     // C columns (deg at col 64)
#define BM 128
#define BK 64
#define KSPLIT 2
#define NITL (NN / BK / KSPLIT)   // 64 k-tiles per CTA
#define SB_STR 88                 // bf16 per sB row (conflict-free ldmatrix)
#define SB_TILE (BK * SB_STR)     // 5632 bf16 = 11264 B
#define SA_BYTES (BM * 128)       // 16384 B per A buffer (swizzled, 128B rows)
#define SMEM_MM (2 * SA_BYTES + 3 * SB_TILE * 2)  // 66560

// device scratch (static allocation only — no cudaMalloc allowed)
__device__ __align__(16) __nv_bfloat16 g_hext[NN * HE];
__device__ __align__(16) float g_Cp[KSPLIT * NN * NTC];

typedef unsigned int uint;

__device__ __forceinline__ void cpa16(void* dst, const void* src) {
    uint32_t d = (uint32_t)__cvta_generic_to_shared(dst);
    asm volatile("cp.async.cg.shared.global [%0], [%1], 16;\n" :: "r"(d), "l"(src));
}

// ---------------------------------------------------------------------------
// K_h: h = x @ Wt^T + bt  ->  g_hext (bf16, 80 cols; col 64 = 1.0, rest 0)
// 8 rows/CTA, 256 thr, 16 KB smem -> 2 CTAs/SM for latency overlap.
// ---------------------------------------------------------------------------
__global__ void __launch_bounds__(256) k_h(const float* __restrict__ x,
                                           const float* __restrict__ Wt,
                                           const float* __restrict__ bt) {
    __shared__ __align__(16) float xs[8][FD];       // 8 KB
    __shared__ float part[4][8][64];                // 8 KB
    const int tid = threadIdx.x;
    const int c = tid & 63;        // output column
    const int fc = tid >> 6;       // f-chunk 0..3 (64 f each)

    float w[64];
    {
        const float4* wr = (const float4*)(Wt + (size_t)c * FD + fc * 64);
#pragma unroll
        for (int j = 0; j < 16; j++) {
            float4 v = wr[j];
            w[4 * j] = v.x; w[4 * j + 1] = v.y; w[4 * j + 2] = v.z; w[4 * j + 3] = v.w;
        }
    }

    const int r0 = blockIdx.x * 8;   // grid 1024 covers 8192
#pragma unroll
    for (int j = 0; j < 8; j++) {
        int i = tid + j * 256;
        int r = i >> 8, f = i & 255;
        xs[r][f] = x[(size_t)(r0 + r) * FD + f];
    }
    __syncthreads();

#pragma unroll
    for (int r = 0; r < 8; r++) {
        const float4* xv = (const float4*)(&xs[r][fc * 64]);
        float p0 = 0.f, p1 = 0.f, p2 = 0.f, p3 = 0.f;
#pragma unroll
        for (int j = 0; j < 16; j += 4) {
            float4 v0 = xv[j], v1 = xv[j + 1], v2 = xv[j + 2], v3 = xv[j + 3];
            p0 += v0.x * w[4 * j + 0] + v0.y * w[4 * j + 1] + v0.z * w[4 * j + 2] + v0.w * w[4 * j + 3];
            p1 += v1.x * w[4 * j + 4] + v1.y * w[4 * j + 5] + v1.z * w[4 * j + 6] + v1.w * w[4 * j + 7];
            p2 += v2.x * w[4 * j + 8] + v2.y * w[4 * j + 9] + v2.z * w[4 * j + 10] + v2.w * w[4 * j + 11];
            p3 += v3.x * w[4 * j + 12] + v3.y * w[4 * j + 13] + v3.z * w[4 * j + 14] + v3.w * w[4 * j + 15];
        }
        part[fc][r][c] = (p0 + p1) + (p2 + p3);
    }
    __syncthreads();

#pragma unroll
    for (int j = 0; j < 2; j++) {
        int i = tid + j * 256;
        int r = i >> 6, cc = i & 63;
        float hv = part[0][r][cc] + part[1][r][cc] + part[2][r][cc] + part[3][r][cc] + bt[cc];
        g_hext[(size_t)(r0 + r) * HE + cc] = __float2bfloat16(hv);
    }
    if (tid < 128) {   // pad cols 64..79 (col 64 = ones for deg)
        int r = tid >> 4, cc = 64 + (tid & 15);
        g_hext[(size_t)(r0 + r) * HE + cc] = __float2bfloat16(cc == HD ? 1.f : 0.f);
    }
}

// ---------------------------------------------------------------------------
// K_mm: Cp[khalf] = adj(0/1 -> bf16) @ h_ext over k-half   (mma.sync m16n8k16)
//  - BM=128, split-K=2 -> grid 128 (1 CTA/SM), 256 thr
//  - A: COALESCED LDG.128 (warp sweeps whole rows -> nL=4 lines/LDG, 256
//    L1 wavefronts/tile instead of 2048) -> reg bf16 pack -> swizzled STS.64
//  - B: 3-stage cp.async ring; warps: mgroup=warp&3 (32 rows), nset=warp>>2
// ---------------------------------------------------------------------------
__device__ __forceinline__ void loadB(__nv_bfloat16* sB, int ktg, int tid) {
#pragma unroll
    for (int j = 0; j < 3; j++) {
        int i = tid + j * 256;          // 640 chunks of 16B (h_ext 64x80 bf16)
        if (i < 640) {
            int r = i / 10, cc = i % 10;
            cpa16(sB + r * SB_STR + cc * 8, g_hext + (size_t)(ktg * BK + r) * HE + cc * 8);
        }
    }
    asm volatile("cp.async.commit_group;\n");
}

__global__ void __launch_bounds__(256) k_adj_mm(const int* __restrict__ adj) {
    extern __shared__ __align__(16) char dyn[];
    char* sA = dyn;                                          // 2 x 16384 B
    __nv_bfloat16* sB0 = (__nv_bfloat16*)(dyn + 2 * SA_BYTES);

    const int tid = threadIdx.x;
    const int warp = tid >> 5, lane = tid & 31;
    const int mtile = blockIdx.x >> 1, khalf = blockIdx.x & 1;
    const int rowBase = mtile * BM;
    const int kbase = khalf * (NN / 2);
    const int mgroup = warp & 3;          // 32-row group
    const int nset = warp >> 2;           // 0: tiles 0-4 (cols 0-39), 1: tiles 5-8

    // A producer mapping (coalesced): thread owns chunk (row = tid>>4 + 16j, c16 = tid&15)
    const int arow = tid >> 4;            // base row 0..15
    const int c16 = tid & 15;             // 16B chunk within the row (4 ints)
    const int* ap = adj + (size_t)(rowBase + arow) * NN + kbase + c16 * 4;

    float acc[2][5][4];
#pragma unroll
    for (int a = 0; a < 2; a++)
#pragma unroll
        for (int i = 0; i < 5; i++)
            acc[a][i][0] = acc[a][i][1] = acc[a][i][2] = acc[a][i][3] = 0.f;

    int4 rA[8];
#pragma unroll
    for (int j = 0; j < 8; j++) rA[j] = *(const int4*)(ap + (size_t)(16 * j) * NN);

    loadB(sB0 + 0 * SB_TILE, khalf * NITL + 0, tid);
    loadB(sB0 + 1 * SB_TILE, khalf * NITL + 1, tid);

    const uint32_t sAu = (uint32_t)__cvta_generic_to_shared(sA);
    // swizzled STS.64 target offset within a row (constant per thread)
    const int sts_row_off = (((c16 >> 1) ^ (arow & 7)) * 16) + (c16 & 1) * 8;

    for (int kt = 0; kt < NITL; ++kt) {
        // pack A regs -> bf16, swizzled STS.64 (8 per thread, conflict-free)
        {
            const uint32_t abase = sAu + (kt & 1) * SA_BYTES;
#pragma unroll
            for (int j = 0; j < 8; j++) {
                int4 v = rA[j];
                uint lo = (uint)v.x * 0x3F80u + (uint)v.y * 0x3F800000u;
                uint hi = (uint)v.z * 0x3F80u + (uint)v.w * 0x3F800000u;
                uint32_t d = abase + (arow + 16 * j) * 128 + sts_row_off;
                asm volatile("st.shared.v2.b32 [%0], {%1, %2};"
                             :: "r"(d), "r"(lo), "r"(hi) : "memory");
            }
        }
        // prefetch A for kt+1 (coalesced)
        if (kt + 1 < NITL) {
            const int* np = ap + (size_t)(kt + 1) * BK;
#pragma unroll
            for (int j = 0; j < 8; j++) rA[j] = *(const int4*)(np + (size_t)(16 * j) * NN);
        }

        asm volatile("cp.async.wait_group 1;\n");
        __syncthreads();
        if (kt + 2 < NITL)
            loadB(sB0 + ((kt + 2) % 3) * SB_TILE, khalf * NITL + kt + 2, tid);

        const __nv_bfloat16* sB = sB0 + (kt % 3) * SB_TILE;
        const uint32_t sAb = sAu + (kt & 1) * SA_BYTES;

#pragma unroll
        for (int ks = 0; ks < 4; ++ks) {
            // A fragments for both m-frags (swizzled ldmatrix)
            uint a[2][4];
#pragma unroll
            for (int mf = 0; mf < 2; mf++) {
                int row = mgroup * 32 + mf * 16 + (lane & 15);
                int chunk = 2 * ks + (lane >> 4);
                uint32_t addr = sAb + row * 128 + ((chunk ^ (lane & 7)) * 16);
                asm volatile("ldmatrix.sync.aligned.m8n8.x4.shared.b16 {%0,%1,%2,%3},[%4];\n"
                             : "=r"(a[mf][0]), "=r"(a[mf][1]), "=r"(a[mf][2]), "=r"(a[mf][3])
                             : "r"(addr));
            }
            const int kk = ks * 16 + (lane & 15);
            if (nset == 0) {
                uint b[10];
#pragma unroll
                for (int pl = 0; pl < 2; pl++) {
                    uint32_t addr = (uint32_t)__cvta_generic_to_shared(
                        &sB[kk * SB_STR + pl * 16 + ((lane >> 4) << 3)]);
                    asm volatile("ldmatrix.sync.aligned.m8n8.x4.trans.shared.b16 {%0,%1,%2,%3},[%4];\n"
                                 : "=r"(b[4 * pl]), "=r"(b[4 * pl + 1]),
                                   "=r"(b[4 * pl + 2]), "=r"(b[4 * pl + 3])
                                 : "r"(addr));
                }
                {
                    uint32_t addr = (uint32_t)__cvta_generic_to_shared(&sB[kk * SB_STR + 32]);
                    asm volatile("ldmatrix.sync.aligned.m8n8.x2.trans.shared.b16 {%0,%1},[%2];\n"
                                 : "=r"(b[8]), "=r"(b[9]) : "r"(addr));
                }
#pragma unroll
                for (int mf = 0; mf < 2; mf++) {
#pragma unroll
                    for (int t = 0; t < 5; t++) {
                        asm volatile("mma.sync.aligned.m16n8k16.row.col.f32.bf16.bf16.f32 "
                                     "{%0,%1,%2,%3},{%4,%5,%6,%7},{%8,%9},{%0,%1,%2,%3};\n"
                                     : "+f"(acc[mf][t][0]), "+f"(acc[mf][t][1]),
                                       "+f"(acc[mf][t][2]), "+f"(acc[mf][t][3])
                                     : "r"(a[mf][0]), "r"(a[mf][1]), "r"(a[mf][2]), "r"(a[mf][3]),
                                       "r"(b[2 * t]), "r"(b[2 * t + 1]));
                    }
                }
            } else {
                uint b[8];
#pragma unroll
                for (int pl = 0; pl < 2; pl++) {
                    uint32_t addr = (uint32_t)__cvta_generic_to_shared(
                        &sB[kk * SB_STR + 40 + pl * 16 + ((lane >> 4) << 3)]);
                    asm volatile("ldmatrix.sync.aligned.m8n8.x4.trans.shared.b16 {%0,%1,%2,%3},[%4];\n"
                                 : "=r"(b[4 * pl]), "=r"(b[4 * pl + 1]),
                                   "=r"(b[4 * pl + 2]), "=r"(b[4 * pl + 3])
                                 : "r"(addr));
                }
#pragma unroll
                for (int mf = 0; mf < 2; mf++) {
#pragma unroll
                    for (int t = 0; t < 4; t++) {
                        asm volatile("mma.sync.aligned.m16n8k16.row.col.f32.bf16.bf16.f32 "
                                     "{%0,%1,%2,%3},{%4,%5,%6,%7},{%8,%9},{%0,%1,%2,%3};\n"
                                     : "+f"(acc[mf][t][0]), "+f"(acc[mf][t][1]),
                                       "+f"(acc[mf][t][2]), "+f"(acc[mf][t][3])
                                     : "r"(a[mf][0]), "r"(a[mf][1]), "r"(a[mf][2]), "r"(a[mf][3]),
                                       "r"(b[2 * t]), "r"(b[2 * t + 1]));
                    }
                }
            }
        }
        // next iter writes the other sA buffer; its pre-mma sync orders the rest.
    }

    // store C tile for this k-half
    float* Cout = g_Cp + (size_t)khalf * NN * NTC;
    const int gr = lane >> 2, gc = (lane & 3) * 2;
    const int ntiles = (nset == 0) ? 5 : 4;
#pragma unroll
    for (int mf = 0; mf < 2; mf++) {
#pragma unroll
        for (int lt = 0; lt < 5; ++lt) {
            if (lt >= ntiles) break;
            const int gt = (nset == 0) ? lt : (5 + lt);
            size_t base = (size_t)(rowBase + mgroup * 32 + mf * 16 + gr) * NTC + gt * 8 + gc;
            Cout[base] = acc[mf][lt][0];
            Cout[base + 1] = acc[mf][lt][1];
            Cout[base + (size_t)8 * NTC] = acc[mf][lt][2];
            Cout[base + (size_t)8 * NTC + 1] = acc[mf][lt][3];
        }
    }
}

// ---------------------------------------------------------------------------
// K_epi: 16 rows per CTA. C = Cp0 + Cp1; neighbor = C[:, :64]/deg;
//        tf = neighbor @ Wp^T + bp; y = x + tf; LayerNorm(y) -> out.
// ---------------------------------------------------------------------------
__global__ void __launch_bounds__(256) k_epi(const float* __restrict__ x,
                                             const float* __restrict__ Wp,
                                             const float* __restrict__ bp,
                                             const float* __restrict__ gamma,
                                             const float* __restrict__ beta,
                                             float* __restrict__ out) {
    __shared__ __align__(16) float nb[16][HD];
    __shared__ float pwS[8][16], pwQ[8][16];
    __shared__ float muS[16], rsS[16];
    const int row0 = blockIdx.x * 16;
    const int t = threadIdx.x;
    const int warp = t >> 5, lane = t & 31;
    const float* C0 = g_Cp;
    const float* C1 = g_Cp + (size_t)NN * NTC;

#pragma unroll
    for (int j = 0; j < 4; j++) {
        int i = t + j * 256;
        int r = i >> 6, cc = i & 63;
        size_t rb = (size_t)(row0 + r) * NTC;
        float deg = C0[rb + HD] + C1[rb + HD];
        float v = C0[rb + cc] + C1[rb + cc];
        nb[r][cc] = (deg > 0.5f) ? v / deg : 0.f;
    }
    __syncthreads();

    float tf[16];
    {
        float b = bp[t];
#pragma unroll
        for (int r = 0; r < 16; r++) tf[r] = b;
    }
    const float4* wp4 = (const float4*)(Wp + (size_t)t * HD);
#pragma unroll
    for (int q = 0; q < 16; q++) {
        float4 w = wp4[q];
#pragma unroll
        for (int r = 0; r < 16; r++) {
            float4 nv = *(const float4*)(&nb[r][q * 4]);
            tf[r] += nv.x * w.x + nv.y * w.y + nv.z * w.z + nv.w * w.w;
        }
    }

    float y[16];
#pragma unroll
    for (int r = 0; r < 16; r++) y[r] = x[(size_t)(row0 + r) * FD + t] + tf[r];

#pragma unroll
    for (int r = 0; r < 16; r++) {
        float s = y[r], q = y[r] * y[r];
#pragma unroll
        for (int o = 16; o > 0; o >>= 1) {
            s += __shfl_xor_sync(0xffffffffu, s, o);
            q += __shfl_xor_sync(0xffffffffu, q, o);
        }
        if (lane == 0) { pwS[warp][r] = s; pwQ[warp][r] = q; }
    }
    __syncthreads();
    if (t < 16) {
        float s = 0.f, q = 0.f;
#pragma unroll
        for (int w = 0; w < 8; w++) { s += pwS[w][t]; q += pwQ[w][t]; }
        float mu = s * (1.f / FD);
        float var = q * (1.f / FD) - mu * mu;
        muS[t] = mu;
        rsS[t] = rsqrtf(var + 1e-5f);
    }
    __syncthreads();

    const float g = gamma[t], b = beta[t];
#pragma unroll
    for (int r = 0; r < 16; r++)
        out[(size_t)(row0 + r) * FD + t] = g * (y[r] - muS[r]) * rsS[r] + b;
}

// ---------------------------------------------------------------------------
extern "C" void kernel_launch(void* const* d_in, const int* in_sizes, int n_in,
                              void* d_out, int out_size) {
    const float* x     = (const float*)d_in[0];
    const int*   adj   = (const int*)d_in[1];
    const float* Wt    = (const float*)d_in[2];
    const float* bt    = (const float*)d_in[3];
    // d_in[4] (Wa), d_in[5] (ba): mathematically irrelevant — softmax over
    // row-constant scores collapses to 1/deg regardless of s.
    const float* Wp    = (const float*)d_in[6];
    const float* bp    = (const float*)d_in[7];
    const float* gamma = (const float*)d_in[8];
    const float* beta  = (const float*)d_in[9];
    float* out = (float*)d_out;

    cudaFuncSetAttribute(k_adj_mm, cudaFuncAttributeMaxDynamicSharedMemorySize, SMEM_MM);
    k_h<<<NN / 8, 256>>>(x, Wt, bt);
    k_adj_mm<<<(NN / BM) * KSPLIT, 256, SMEM_MM>>>(adj);
    k_epi<<<NN / 16, 256>>>(x, Wp, bp, gamma, beta, out);
}

// round 10
// speedup vs baseline: 3.0061x; 1.2622x over previous
#include <cuda_runtime.h>
#include <cuda_bf16.h>
#include <cstdint>

#define NN 8192
#define FD 256
#define HD 64
#define HE 80      // h_ext columns (64 h + ones col 64 + 15 zero)
#define NTC 72     // C columns (deg at col 64)
#define BM 128
#define BK 64
#define KSPLIT 4
#define NITL (NN / BK / KSPLIT)   // 32 k-tiles per CTA
#define SB_STR 88                 // bf16 per sB row (conflict-free ldmatrix)
#define SB_TILE (BK * SB_STR)     // 5632 bf16 = 11264 B
#define SA_BYTES (BM * 128)       // 16384 B per A buffer (swizzled, 128B rows)
#define SMEM_MM (2 * SA_BYTES + 3 * SB_TILE * 2)  // 66560

// device scratch (static allocation only — no cudaMalloc allowed)
__device__ __align__(16) __nv_bfloat16 g_hext[NN * HE];
__device__ __align__(16) float g_Cp[KSPLIT * NN * NTC];

typedef unsigned int uint;

__device__ __forceinline__ void cpa16(void* dst, const void* src) {
    uint32_t d = (uint32_t)__cvta_generic_to_shared(dst);
    asm volatile("cp.async.cg.shared.global [%0], [%1], 16;\n" :: "r"(d), "l"(src));
}

// ---------------------------------------------------------------------------
// K_h: h = x @ Wt^T + bt  ->  g_hext (bf16, 80 cols; col 64 = 1.0, rest 0)
// 32 rows/CTA (grid 256): 4x work per weight-register set, deep cross-row ILP.
// ---------------------------------------------------------------------------
__global__ void __launch_bounds__(256, 2) k_h(const float* __restrict__ x,
                                              const float* __restrict__ Wt,
                                              const float* __restrict__ bt) {
    __shared__ __align__(16) float xs[32][FD];      // 32 KB
    __shared__ float part[4][32][64];               // 32 KB
    const int tid = threadIdx.x;
    const int c = tid & 63;        // output column
    const int fc = tid >> 6;       // f-chunk 0..3 (64 f each)

    float w[64];
    {
        const float4* wr = (const float4*)(Wt + (size_t)c * FD + fc * 64);
#pragma unroll
        for (int j = 0; j < 16; j++) {
            float4 v = wr[j];
            w[4 * j] = v.x; w[4 * j + 1] = v.y; w[4 * j + 2] = v.z; w[4 * j + 3] = v.w;
        }
    }

    const int r0 = blockIdx.x * 32;   // grid 256 covers 8192
    {
        const float4* xsrc = (const float4*)(x + (size_t)r0 * FD);
        float4* xd = (float4*)xs;
#pragma unroll
        for (int j = 0; j < 8; j++) xd[tid + j * 256] = xsrc[tid + j * 256];
    }
    __syncthreads();

#pragma unroll 4
    for (int r = 0; r < 32; r++) {
        const float4* xv = (const float4*)(&xs[r][fc * 64]);
        float p0 = 0.f, p1 = 0.f, p2 = 0.f, p3 = 0.f;
#pragma unroll
        for (int j = 0; j < 16; j += 4) {
            float4 v0 = xv[j], v1 = xv[j + 1], v2 = xv[j + 2], v3 = xv[j + 3];
            p0 += v0.x * w[4 * j + 0] + v0.y * w[4 * j + 1] + v0.z * w[4 * j + 2] + v0.w * w[4 * j + 3];
            p1 += v1.x * w[4 * j + 4] + v1.y * w[4 * j + 5] + v1.z * w[4 * j + 6] + v1.w * w[4 * j + 7];
            p2 += v2.x * w[4 * j + 8] + v2.y * w[4 * j + 9] + v2.z * w[4 * j + 10] + v2.w * w[4 * j + 11];
            p3 += v3.x * w[4 * j + 12] + v3.y * w[4 * j + 13] + v3.z * w[4 * j + 14] + v3.w * w[4 * j + 15];
        }
        part[fc][r][c] = (p0 + p1) + (p2 + p3);
    }
    __syncthreads();

#pragma unroll
    for (int j = 0; j < 8; j++) {
        int i = tid + j * 256;
        int r = i >> 6, cc = i & 63;
        float hv = part[0][r][cc] + part[1][r][cc] + part[2][r][cc] + part[3][r][cc] + bt[cc];
        g_hext[(size_t)(r0 + r) * HE + cc] = __float2bfloat16(hv);
    }
#pragma unroll
    for (int j = 0; j < 2; j++) {   // pad cols 64..79 (col 64 = ones for deg)
        int i = tid + j * 256;
        int r = i >> 4, cc = 64 + (i & 15);
        g_hext[(size_t)(r0 + r) * HE + cc] = __float2bfloat16(cc == HD ? 1.f : 0.f);
    }
}

// ---------------------------------------------------------------------------
// K_mm: Cp[kq] = adj(0/1 -> bf16) @ h_ext over k-quarter   (mma.sync m16n8k16)
//  - BM=128, split-K=4 -> grid 256, 2 CTAs/SM (phase overlap across CTAs)
//  - A: coalesced LDG.128 (nL=4) -> reg bf16 pack -> swizzled STS.64
//  - B: 3-stage cp.async ring; warps: mgroup=warp&3 (32 rows), nset=warp>>2
// ---------------------------------------------------------------------------
__device__ __forceinline__ void loadB(__nv_bfloat16* sB, int ktg, int tid) {
#pragma unroll
    for (int j = 0; j < 3; j++) {
        int i = tid + j * 256;          // 640 chunks of 16B (h_ext 64x80 bf16)
        if (i < 640) {
            int r = i / 10, cc = i % 10;
            cpa16(sB + r * SB_STR + cc * 8, g_hext + (size_t)(ktg * BK + r) * HE + cc * 8);
        }
    }
    asm volatile("cp.async.commit_group;\n");
}

__global__ void __launch_bounds__(256, 2) k_adj_mm(const int* __restrict__ adj) {
    extern __shared__ __align__(16) char dyn[];
    char* sA = dyn;                                          // 2 x 16384 B
    __nv_bfloat16* sB0 = (__nv_bfloat16*)(dyn + 2 * SA_BYTES);

    const int tid = threadIdx.x;
    const int warp = tid >> 5, lane = tid & 31;
    const int mtile = blockIdx.x >> 2, kq = blockIdx.x & 3;
    const int rowBase = mtile * BM;
    const int kbase = kq * (NN / KSPLIT);
    const int mgroup = warp & 3;          // 32-row group
    const int nset = warp >> 2;           // 0: tiles 0-4 (cols 0-39), 1: tiles 5-8

    // A producer mapping (coalesced): thread owns chunk (row = tid>>4 + 16j, c16 = tid&15)
    const int arow = tid >> 4;            // base row 0..15
    const int c16 = tid & 15;             // 16B chunk within the row (4 ints)
    const int* ap = adj + (size_t)(rowBase + arow) * NN + kbase + c16 * 4;

    float acc[2][5][4];
#pragma unroll
    for (int a = 0; a < 2; a++)
#pragma unroll
        for (int i = 0; i < 5; i++)
            acc[a][i][0] = acc[a][i][1] = acc[a][i][2] = acc[a][i][3] = 0.f;

    int4 rA[8];
#pragma unroll
    for (int j = 0; j < 8; j++) rA[j] = *(const int4*)(ap + (size_t)(16 * j) * NN);

    loadB(sB0 + 0 * SB_TILE, kq * NITL + 0, tid);
    loadB(sB0 + 1 * SB_TILE, kq * NITL + 1, tid);

    const uint32_t sAu = (uint32_t)__cvta_generic_to_shared(sA);
    // swizzled STS.64 target offset within a row (constant per thread)
    const int sts_row_off = (((c16 >> 1) ^ (arow & 7)) * 16) + (c16 & 1) * 8;

    for (int kt = 0; kt < NITL; ++kt) {
        // pack A regs -> bf16, swizzled STS.64 (8 per thread, conflict-free)
        {
            const uint32_t abase = sAu + (kt & 1) * SA_BYTES;
#pragma unroll
            for (int j = 0; j < 8; j++) {
                int4 v = rA[j];
                uint lo = (uint)v.x * 0x3F80u + (uint)v.y * 0x3F800000u;
                uint hi = (uint)v.z * 0x3F80u + (uint)v.w * 0x3F800000u;
                uint32_t d = abase + (arow + 16 * j) * 128 + sts_row_off;
                asm volatile("st.shared.v2.b32 [%0], {%1, %2};"
                             :: "r"(d), "r"(lo), "r"(hi) : "memory");
            }
        }
        // prefetch A for kt+1 (coalesced)
        if (kt + 1 < NITL) {
            const int* np = ap + (size_t)(kt + 1) * BK;
#pragma unroll
            for (int j = 0; j < 8; j++) rA[j] = *(const int4*)(np + (size_t)(16 * j) * NN);
        }

        asm volatile("cp.async.wait_group 1;\n");
        __syncthreads();
        if (kt + 2 < NITL)
            loadB(sB0 + ((kt + 2) % 3) * SB_TILE, kq * NITL + kt + 2, tid);

        const __nv_bfloat16* sB = sB0 + (kt % 3) * SB_TILE;
        const uint32_t sAb = sAu + (kt & 1) * SA_BYTES;

#pragma unroll
        for (int ks = 0; ks < 4; ++ks) {
            // A fragments for both m-frags (swizzled ldmatrix)
            uint a[2][4];
#pragma unroll
            for (int mf = 0; mf < 2; mf++) {
                int row = mgroup * 32 + mf * 16 + (lane & 15);
                int chunk = 2 * ks + (lane >> 4);
                uint32_t addr = sAb + row * 128 + ((chunk ^ (lane & 7)) * 16);
                asm volatile("ldmatrix.sync.aligned.m8n8.x4.shared.b16 {%0,%1,%2,%3},[%4];\n"
                             : "=r"(a[mf][0]), "=r"(a[mf][1]), "=r"(a[mf][2]), "=r"(a[mf][3])
                             : "r"(addr));
            }
            const int kk = ks * 16 + (lane & 15);
            if (nset == 0) {
                uint b[10];
#pragma unroll
                for (int pl = 0; pl < 2; pl++) {
                    uint32_t addr = (uint32_t)__cvta_generic_to_shared(
                        &sB[kk * SB_STR + pl * 16 + ((lane >> 4) << 3)]);
                    asm volatile("ldmatrix.sync.aligned.m8n8.x4.trans.shared.b16 {%0,%1,%2,%3},[%4];\n"
                                 : "=r"(b[4 * pl]), "=r"(b[4 * pl + 1]),
                                   "=r"(b[4 * pl + 2]), "=r"(b[4 * pl + 3])
                                 : "r"(addr));
                }
                {
                    uint32_t addr = (uint32_t)__cvta_generic_to_shared(&sB[kk * SB_STR + 32]);
                    asm volatile("ldmatrix.sync.aligned.m8n8.x2.trans.shared.b16 {%0,%1},[%2];\n"
                                 : "=r"(b[8]), "=r"(b[9]) : "r"(addr));
                }
#pragma unroll
                for (int mf = 0; mf < 2; mf++) {
#pragma unroll
                    for (int t = 0; t < 5; t++) {
                        asm volatile("mma.sync.aligned.m16n8k16.row.col.f32.bf16.bf16.f32 "
                                     "{%0,%1,%2,%3},{%4,%5,%6,%7},{%8,%9},{%0,%1,%2,%3};\n"
                                     : "+f"(acc[mf][t][0]), "+f"(acc[mf][t][1]),
                                       "+f"(acc[mf][t][2]), "+f"(acc[mf][t][3])
                                     : "r"(a[mf][0]), "r"(a[mf][1]), "r"(a[mf][2]), "r"(a[mf][3]),
                                       "r"(b[2 * t]), "r"(b[2 * t + 1]));
                    }
                }
            } else {
                uint b[8];
#pragma unroll
                for (int pl = 0; pl < 2; pl++) {
                    uint32_t addr = (uint32_t)__cvta_generic_to_shared(
                        &sB[kk * SB_STR + 40 + pl * 16 + ((lane >> 4) << 3)]);
                    asm volatile("ldmatrix.sync.aligned.m8n8.x4.trans.shared.b16 {%0,%1,%2,%3},[%4];\n"
                                 : "=r"(b[4 * pl]), "=r"(b[4 * pl + 1]),
                                   "=r"(b[4 * pl + 2]), "=r"(b[4 * pl + 3])
                                 : "r"(addr));
                }
#pragma unroll
                for (int mf = 0; mf < 2; mf++) {
#pragma unroll
                    for (int t = 0; t < 4; t++) {
                        asm volatile("mma.sync.aligned.m16n8k16.row.col.f32.bf16.bf16.f32 "
                                     "{%0,%1,%2,%3},{%4,%5,%6,%7},{%8,%9},{%0,%1,%2,%3};\n"
                                     : "+f"(acc[mf][t][0]), "+f"(acc[mf][t][1]),
                                       "+f"(acc[mf][t][2]), "+f"(acc[mf][t][3])
                                     : "r"(a[mf][0]), "r"(a[mf][1]), "r"(a[mf][2]), "r"(a[mf][3]),
                                       "r"(b[2 * t]), "r"(b[2 * t + 1]));
                    }
                }
            }
        }
        // next iter writes the other sA buffer; its pre-mma sync orders the rest.
    }

    // store C tile for this k-quarter
    float* Cout = g_Cp + (size_t)kq * NN * NTC;
    const int gr = lane >> 2, gc = (lane & 3) * 2;
    const int ntiles = (nset == 0) ? 5 : 4;
#pragma unroll
    for (int mf = 0; mf < 2; mf++) {
#pragma unroll
        for (int lt = 0; lt < 5; ++lt) {
            if (lt >= ntiles) break;
            const int gt = (nset == 0) ? lt : (5 + lt);
            size_t base = (size_t)(rowBase + mgroup * 32 + mf * 16 + gr) * NTC + gt * 8 + gc;
            Cout[base] = acc[mf][lt][0];
            Cout[base + 1] = acc[mf][lt][1];
            Cout[base + (size_t)8 * NTC] = acc[mf][lt][2];
            Cout[base + (size_t)8 * NTC + 1] = acc[mf][lt][3];
        }
    }
}

// ---------------------------------------------------------------------------
// K_epi: 16 rows per CTA. C = sum of 4 k-quarter partials; neighbor = C/deg;
//        tf = neighbor @ Wp^T + bp; y = x + tf; LayerNorm(y) -> out.
// ---------------------------------------------------------------------------
__global__ void __launch_bounds__(256) k_epi(const float* __restrict__ x,
                                             const float* __restrict__ Wp,
                                             const float* __restrict__ bp,
                                             const float* __restrict__ gamma,
                                             const float* __restrict__ beta,
                                             float* __restrict__ out) {
    __shared__ __align__(16) float nb[16][HD];
    __shared__ float pwS[8][16], pwQ[8][16];
    __shared__ float muS[16], rsS[16];
    const int row0 = blockIdx.x * 16;
    const int t = threadIdx.x;
    const int warp = t >> 5, lane = t & 31;

#pragma unroll
    for (int j = 0; j < 4; j++) {
        int i = t + j * 256;
        int r = i >> 6, cc = i & 63;
        size_t rb = (size_t)(row0 + r) * NTC;
        float deg = 0.f, v = 0.f;
#pragma unroll
        for (int q = 0; q < KSPLIT; q++) {
            const float* Cq = g_Cp + (size_t)q * NN * NTC;
            deg += Cq[rb + HD];
            v += Cq[rb + cc];
        }
        nb[r][cc] = (deg > 0.5f) ? v / deg : 0.f;
    }
    __syncthreads();

    float tf[16];
    {
        float b = bp[t];
#pragma unroll
        for (int r = 0; r < 16; r++) tf[r] = b;
    }
    const float4* wp4 = (const float4*)(Wp + (size_t)t * HD);
#pragma unroll
    for (int q = 0; q < 16; q++) {
        float4 w = wp4[q];
#pragma unroll
        for (int r = 0; r < 16; r++) {
            float4 nv = *(const float4*)(&nb[r][q * 4]);
            tf[r] += nv.x * w.x + nv.y * w.y + nv.z * w.z + nv.w * w.w;
        }
    }

    float y[16];
#pragma unroll
    for (int r = 0; r < 16; r++) y[r] = x[(size_t)(row0 + r) * FD + t] + tf[r];

#pragma unroll
    for (int r = 0; r < 16; r++) {
        float s = y[r], q = y[r] * y[r];
#pragma unroll
        for (int o = 16; o > 0; o >>= 1) {
            s += __shfl_xor_sync(0xffffffffu, s, o);
            q += __shfl_xor_sync(0xffffffffu, q, o);
        }
        if (lane == 0) { pwS[warp][r] = s; pwQ[warp][r] = q; }
    }
    __syncthreads();
    if (t < 16) {
        float s = 0.f, q = 0.f;
#pragma unroll
        for (int w = 0; w < 8; w++) { s += pwS[w][t]; q += pwQ[w][t]; }
        float mu = s * (1.f / FD);
        float var = q * (1.f / FD) - mu * mu;
        muS[t] = mu;
        rsS[t] = rsqrtf(var + 1e-5f);
    }
    __syncthreads();

    const float g = gamma[t], b = beta[t];
#pragma unroll
    for (int r = 0; r < 16; r++)
        out[(size_t)(row0 + r) * FD + t] = g * (y[r] - muS[r]) * rsS[r] + b;
}

// ---------------------------------------------------------------------------
extern "C" void kernel_launch(void* const* d_in, const int* in_sizes, int n_in,
                              void* d_out, int out_size) {
    const float* x     = (const float*)d_in[0];
    const int*   adj   = (const int*)d_in[1];
    const float* Wt    = (const float*)d_in[2];
    const float* bt    = (const float*)d_in[3];
    // d_in[4] (Wa), d_in[5] (ba): mathematically irrelevant — softmax over
    // row-constant scores collapses to 1/deg regardless of s.
    const float* Wp    = (const float*)d_in[6];
    const float* bp    = (const float*)d_in[7];
    const float* gamma = (const float*)d_in[8];
    const float* beta  = (const float*)d_in[9];
    float* out = (float*)d_out;

    cudaFuncSetAttribute(k_adj_mm, cudaFuncAttributeMaxDynamicSharedMemorySize, SMEM_MM);
    k_h<<<NN / 32, 256>>>(x, Wt, bt);
    k_adj_mm<<<(NN / BM) * KSPLIT, 256, SMEM_MM>>>(adj);
    k_epi<<<NN / 16, 256>>>(x, Wp, bp, gamma, beta, out);
}